// round 3
// baseline (speedup 1.0000x reference)
#include <cuda_runtime.h>

// LSTMAnomalyDetector: B=4096, T=512, I=3, H=64 (PyTorch gate order i,f,g,o)
// Persistent CTA: 128 CTAs x 512 threads, 32 batch rows per CTA, all 512 steps on-chip.
//
// Round-3: thread owns (1 unit x 4 rows). 16 warps/SM (4 per SMSP) to hide LDS
// latency; 8 fma2 accumulators; per k: 3 LDS.128 + 8 fma.rn.f32x2.
// W_hh pre-duplicated in smem as (w,w) pairs -> no packing MOVs in the hot loop.

#define B_  4096
#define T_  512
#define H_  64
#define RT  32       // rows per CTA
#define NT  512      // threads per CTA
#define HP  36       // hsh row pitch in floats

typedef unsigned long long ull;

__device__ __forceinline__ float tanhfast(float x) {
    float y; asm("tanh.approx.f32 %0, %1;" : "=f"(y) : "f"(x)); return y;
}
__device__ __forceinline__ float sigf(float x) {
    return fmaf(0.5f, tanhfast(0.5f * x), 0.5f);
}
__device__ __forceinline__ ull pack2(float a, float b) {
    ull r; asm("mov.b64 %0, {%1, %2};" : "=l"(r) : "f"(a), "f"(b)); return r;
}
__device__ __forceinline__ void unpack2(ull v, float& lo, float& hi) {
    asm("mov.b64 {%0, %1}, %2;" : "=f"(lo), "=f"(hi) : "l"(v));
}
__device__ __forceinline__ ull fma2(ull a, ull b, ull c) {
    ull d; asm("fma.rn.f32x2 %0, %1, %2, %3;" : "=l"(d) : "l"(a), "l"(b), "l"(c)); return d;
}

struct Smem {
    ulonglong2 W01[H_][H_];   // 64KB  [k][u]: ((wi,wi),(wf,wf))
    ulonglong2 W23[H_][H_];   // 64KB  [k][u]: ((wg,wg),(wo,wo))
    float hsh[2][H_][HP];     // [buf][unit k][row], pitch 36
    float xsh[2][3][RT];      // x double buffer, transposed [i][row]
    float wdec[3][H_];
};
#define SMEM_BYTES ((int)sizeof(Smem))

extern __shared__ char smem_raw[];

__global__ void __launch_bounds__(NT, 1)
lstm_persistent_kernel(const float* __restrict__ x,      // [B, T, 3]
                       const float* __restrict__ Wih,    // [256, 3]
                       const float* __restrict__ Whh,    // [256, 64]
                       const float* __restrict__ bih,    // [256]
                       const float* __restrict__ bhh,    // [256]
                       const float* __restrict__ Wdec,   // [3, 64]
                       const float* __restrict__ bdec,   // [3]
                       float* __restrict__ out)          // [B, T, 3]
{
    Smem* S = (Smem*)smem_raw;
    const int tid  = threadIdx.x;
    const int row0 = blockIdx.x * RT;

    const int u  = tid >> 3;        // unit 0..63 owned by this thread
    const int rg = tid & 7;         // row group: rows 4rg .. 4rg+3

    // ---- setup -----------------------------------------------------------
    for (int idx = tid; idx < H_ * H_; idx += NT) {
        const int k = idx >> 6, uu = idx & 63;
        const float wi = Whh[(0 * H_ + uu) * H_ + k];
        const float wf = Whh[(1 * H_ + uu) * H_ + k];
        const float wg = Whh[(2 * H_ + uu) * H_ + k];
        const float wo = Whh[(3 * H_ + uu) * H_ + k];
        *(float4*)&S->W01[k][uu] = make_float4(wi, wi, wf, wf);
        *(float4*)&S->W23[k][uu] = make_float4(wg, wg, wo, wo);
    }
    for (int i = tid; i < 2 * H_ * HP; i += NT) ((float*)S->hsh)[i] = 0.0f;
    if (tid < 3 * H_) ((float*)S->wdec)[tid] = Wdec[tid];

    // per-thread W_ih (duplicated) and bias in registers
    ull wih2[4][3], biasp[4];
#pragma unroll
    for (int gt = 0; gt < 4; gt++) {
        const int g = gt * H_ + u;
        const float b = bih[g] + bhh[g];
        biasp[gt] = pack2(b, b);
#pragma unroll
        for (int i = 0; i < 3; i++) {
            const float wv = Wih[g * 3 + i];
            wih2[gt][i] = pack2(wv, wv);
        }
    }

    // decode / x-staging roles (threads 0..95)
    const int dro = tid >> 5;       // output/x component (0..2) for tid<96
    const int drr = tid & 31;       // row
    float bd = 0.0f;
    if (tid < 96) {
        bd = bdec[dro];
        S->xsh[0][dro][drr] = x[((size_t)(row0 + drr) * T_ + 0) * 3 + dro];
    }

    float c[4];
#pragma unroll
    for (int p = 0; p < 4; p++) c[p] = 0.0f;

    __syncthreads();

    // ---- timestep loop -----------------------------------------------------
    for (int t = 0; t < T_; t++) {
        const int A = t & 1, Bb = A ^ 1;

        // prefetch x(t+1): global latency hidden under the matvec
        float xp = 0.0f;
        if (tid < 96 && (t + 1) < T_)
            xp = x[((size_t)(row0 + drr) * T_ + (t + 1)) * 3 + dro];

        // decode previous step's h -> out[., t-1, .]
        if (t > 0 && tid < 96) {
            const float* hp_ = &S->hsh[A][0][drr];
            const float* wd  = &S->wdec[dro][0];
            float s0 = 0.f, s1 = 0.f, s2 = 0.f, s3 = 0.f;
#pragma unroll 4
            for (int k = 0; k < H_; k += 4) {
                s0 = fmaf(hp_[(k + 0) * HP], wd[k + 0], s0);
                s1 = fmaf(hp_[(k + 1) * HP], wd[k + 1], s1);
                s2 = fmaf(hp_[(k + 2) * HP], wd[k + 2], s2);
                s3 = fmaf(hp_[(k + 3) * HP], wd[k + 3], s3);
            }
            out[((size_t)(row0 + drr) * T_ + (t - 1)) * 3 + dro] = (s0 + s1) + (s2 + s3) + bd;
        }

        // accumulators: a[gate][pair]; pair 0 = rows (4rg,4rg+1), pair 1 = rows (4rg+2,4rg+3)
        ull a0[2], a1[2], a2[2], a3[2];
        a0[0] = biasp[0]; a0[1] = biasp[0];
        a1[0] = biasp[1]; a1[1] = biasp[1];
        a2[0] = biasp[2]; a2[1] = biasp[2];
        a3[0] = biasp[3]; a3[1] = biasp[3];

        // input contribution: + W_ih * x(t)
#pragma unroll
        for (int i = 0; i < 3; i++) {
            const ulonglong2 xv = *(const ulonglong2*)&S->xsh[A][i][4 * rg];
            a0[0] = fma2(xv.x, wih2[0][i], a0[0]);  a0[1] = fma2(xv.y, wih2[0][i], a0[1]);
            a1[0] = fma2(xv.x, wih2[1][i], a1[0]);  a1[1] = fma2(xv.y, wih2[1][i], a1[1]);
            a2[0] = fma2(xv.x, wih2[2][i], a2[0]);  a2[1] = fma2(xv.y, wih2[2][i], a2[1]);
            a3[0] = fma2(xv.x, wih2[3][i], a3[0]);  a3[1] = fma2(xv.y, wih2[3][i], a3[1]);
        }

        // recurrent matvec: per k, 3x LDS.128 + 8x fma.rn.f32x2
        {
            const float* hrow = &S->hsh[A][0][4 * rg];
            const ulonglong2* w01p = &S->W01[0][u];
            const ulonglong2* w23p = &S->W23[0][u];
#pragma unroll 4
            for (int k = 0; k < H_; k++) {
                const ulonglong2 hv  = *(const ulonglong2*)(hrow);   // 4 rows
                const ulonglong2 w01 = w01p[k * H_];
                const ulonglong2 w23 = w23p[k * H_];
                a0[0] = fma2(hv.x, w01.x, a0[0]);
                a0[1] = fma2(hv.y, w01.x, a0[1]);
                a1[0] = fma2(hv.x, w01.y, a1[0]);
                a1[1] = fma2(hv.y, w01.y, a1[1]);
                a2[0] = fma2(hv.x, w23.x, a2[0]);
                a2[1] = fma2(hv.y, w23.x, a2[1]);
                a3[0] = fma2(hv.x, w23.y, a3[0]);
                a3[1] = fma2(hv.y, w23.y, a3[1]);
                hrow += HP;
            }
        }

        // nonlinearities + state update on 4 (row, unit u) cells
        float hout[4];
#pragma unroll
        for (int pr = 0; pr < 2; pr++) {
            float gi0, gi1, gf0, gf1, gg0, gg1, go0, go1;
            unpack2(a0[pr], gi0, gi1);
            unpack2(a1[pr], gf0, gf1);
            unpack2(a2[pr], gg0, gg1);
            unpack2(a3[pr], go0, go1);
            {
                const float ig = sigf(gi0), fg = sigf(gf0), gg = tanhfast(gg0), og = sigf(go0);
                const float cn = fmaf(fg, c[2 * pr], ig * gg);
                c[2 * pr] = cn;
                hout[2 * pr] = og * tanhfast(cn);
            }
            {
                const float ig = sigf(gi1), fg = sigf(gf1), gg = tanhfast(gg1), og = sigf(go1);
                const float cn = fmaf(fg, c[2 * pr + 1], ig * gg);
                c[2 * pr + 1] = cn;
                hout[2 * pr + 1] = og * tanhfast(cn);
            }
        }
        *(float4*)&S->hsh[Bb][u][4 * rg] = make_float4(hout[0], hout[1], hout[2], hout[3]);

        // stage x(t+1)
        if (tid < 96) S->xsh[Bb][dro][drr] = xp;

        __syncthreads();
    }

    // epilogue: decode h(T-1) (buffer 0 after the last flip)
    if (tid < 96) {
        const float* hp_ = &S->hsh[0][0][drr];
        const float* wd  = &S->wdec[dro][0];
        float s0 = 0.f, s1 = 0.f, s2 = 0.f, s3 = 0.f;
#pragma unroll 4
        for (int k = 0; k < H_; k += 4) {
            s0 = fmaf(hp_[(k + 0) * HP], wd[k + 0], s0);
            s1 = fmaf(hp_[(k + 1) * HP], wd[k + 1], s1);
            s2 = fmaf(hp_[(k + 2) * HP], wd[k + 2], s2);
            s3 = fmaf(hp_[(k + 3) * HP], wd[k + 3], s3);
        }
        out[((size_t)(row0 + drr) * T_ + (T_ - 1)) * 3 + dro] = (s0 + s1) + (s2 + s3) + bd;
    }
}

extern "C" void kernel_launch(void* const* d_in, const int* in_sizes, int n_in,
                              void* d_out, int out_size) {
    const float* x    = (const float*)d_in[0];
    const float* Wih  = (const float*)d_in[1];
    const float* Whh  = (const float*)d_in[2];
    const float* bih  = (const float*)d_in[3];
    const float* bhh  = (const float*)d_in[4];
    const float* Wdec = (const float*)d_in[5];
    const float* bdec = (const float*)d_in[6];
    float* out = (float*)d_out;

    cudaFuncSetAttribute(lstm_persistent_kernel,
                         cudaFuncAttributeMaxDynamicSharedMemorySize, SMEM_BYTES);
    lstm_persistent_kernel<<<B_ / RT, NT, SMEM_BYTES>>>(x, Wih, Whh, bih, bhh, Wdec, bdec, out);
}

// round 4
// speedup vs baseline: 1.0012x; 1.0012x over previous
#include <cuda_runtime.h>

// LSTMAnomalyDetector: B=4096, T=512, I=3, H=64 (PyTorch gate order i,f,g,o)
// Persistent CTA: 128 CTAs x 512 threads, 32 batch rows per CTA, all 512 steps on-chip.
//
// Round-3: thread owns (1 unit x 4 rows). 16 warps/SM (4 per SMSP) to hide LDS
// latency; 8 fma2 accumulators; per k: 3 LDS.128 + 8 fma.rn.f32x2.
// W_hh pre-duplicated in smem as (w,w) pairs -> no packing MOVs in the hot loop.

#define B_  4096
#define T_  512
#define H_  64
#define RT  32       // rows per CTA
#define NT  512      // threads per CTA
#define HP  36       // hsh row pitch in floats

typedef unsigned long long ull;

__device__ __forceinline__ float tanhfast(float x) {
    float y; asm("tanh.approx.f32 %0, %1;" : "=f"(y) : "f"(x)); return y;
}
__device__ __forceinline__ float sigf(float x) {
    return fmaf(0.5f, tanhfast(0.5f * x), 0.5f);
}
__device__ __forceinline__ ull pack2(float a, float b) {
    ull r; asm("mov.b64 %0, {%1, %2};" : "=l"(r) : "f"(a), "f"(b)); return r;
}
__device__ __forceinline__ void unpack2(ull v, float& lo, float& hi) {
    asm("mov.b64 {%0, %1}, %2;" : "=f"(lo), "=f"(hi) : "l"(v));
}
__device__ __forceinline__ ull fma2(ull a, ull b, ull c) {
    ull d; asm("fma.rn.f32x2 %0, %1, %2, %3;" : "=l"(d) : "l"(a), "l"(b), "l"(c)); return d;
}

struct Smem {
    ulonglong2 W01[H_][H_];   // 64KB  [k][u]: ((wi,wi),(wf,wf))
    ulonglong2 W23[H_][H_];   // 64KB  [k][u]: ((wg,wg),(wo,wo))
    float hsh[2][H_][HP];     // [buf][unit k][row], pitch 36
    float xsh[2][3][RT];      // x double buffer, transposed [i][row]
    float wdec[3][H_];
};
#define SMEM_BYTES ((int)sizeof(Smem))

extern __shared__ char smem_raw[];

__global__ void __launch_bounds__(NT, 1)
lstm_persistent_kernel(const float* __restrict__ x,      // [B, T, 3]
                       const float* __restrict__ Wih,    // [256, 3]
                       const float* __restrict__ Whh,    // [256, 64]
                       const float* __restrict__ bih,    // [256]
                       const float* __restrict__ bhh,    // [256]
                       const float* __restrict__ Wdec,   // [3, 64]
                       const float* __restrict__ bdec,   // [3]
                       float* __restrict__ out)          // [B, T, 3]
{
    Smem* S = (Smem*)smem_raw;
    const int tid  = threadIdx.x;
    const int row0 = blockIdx.x * RT;

    const int u  = tid >> 3;        // unit 0..63 owned by this thread
    const int rg = tid & 7;         // row group: rows 4rg .. 4rg+3

    // ---- setup -----------------------------------------------------------
    for (int idx = tid; idx < H_ * H_; idx += NT) {
        const int k = idx >> 6, uu = idx & 63;
        const float wi = Whh[(0 * H_ + uu) * H_ + k];
        const float wf = Whh[(1 * H_ + uu) * H_ + k];
        const float wg = Whh[(2 * H_ + uu) * H_ + k];
        const float wo = Whh[(3 * H_ + uu) * H_ + k];
        *(float4*)&S->W01[k][uu] = make_float4(wi, wi, wf, wf);
        *(float4*)&S->W23[k][uu] = make_float4(wg, wg, wo, wo);
    }
    for (int i = tid; i < 2 * H_ * HP; i += NT) ((float*)S->hsh)[i] = 0.0f;
    if (tid < 3 * H_) ((float*)S->wdec)[tid] = Wdec[tid];

    // per-thread W_ih (duplicated) and bias in registers
    ull wih2[4][3], biasp[4];
#pragma unroll
    for (int gt = 0; gt < 4; gt++) {
        const int g = gt * H_ + u;
        const float b = bih[g] + bhh[g];
        biasp[gt] = pack2(b, b);
#pragma unroll
        for (int i = 0; i < 3; i++) {
            const float wv = Wih[g * 3 + i];
            wih2[gt][i] = pack2(wv, wv);
        }
    }

    // decode / x-staging roles (threads 0..95)
    const int dro = tid >> 5;       // output/x component (0..2) for tid<96
    const int drr = tid & 31;       // row
    float bd = 0.0f;
    if (tid < 96) {
        bd = bdec[dro];
        S->xsh[0][dro][drr] = x[((size_t)(row0 + drr) * T_ + 0) * 3 + dro];
    }

    float c[4];
#pragma unroll
    for (int p = 0; p < 4; p++) c[p] = 0.0f;

    __syncthreads();

    // ---- timestep loop -----------------------------------------------------
    for (int t = 0; t < T_; t++) {
        const int A = t & 1, Bb = A ^ 1;

        // prefetch x(t+1): global latency hidden under the matvec
        float xp = 0.0f;
        if (tid < 96 && (t + 1) < T_)
            xp = x[((size_t)(row0 + drr) * T_ + (t + 1)) * 3 + dro];

        // decode previous step's h -> out[., t-1, .]
        if (t > 0 && tid < 96) {
            const float* hp_ = &S->hsh[A][0][drr];
            const float* wd  = &S->wdec[dro][0];
            float s0 = 0.f, s1 = 0.f, s2 = 0.f, s3 = 0.f;
#pragma unroll 4
            for (int k = 0; k < H_; k += 4) {
                s0 = fmaf(hp_[(k + 0) * HP], wd[k + 0], s0);
                s1 = fmaf(hp_[(k + 1) * HP], wd[k + 1], s1);
                s2 = fmaf(hp_[(k + 2) * HP], wd[k + 2], s2);
                s3 = fmaf(hp_[(k + 3) * HP], wd[k + 3], s3);
            }
            out[((size_t)(row0 + drr) * T_ + (t - 1)) * 3 + dro] = (s0 + s1) + (s2 + s3) + bd;
        }

        // accumulators: a[gate][pair]; pair 0 = rows (4rg,4rg+1), pair 1 = rows (4rg+2,4rg+3)
        ull a0[2], a1[2], a2[2], a3[2];
        a0[0] = biasp[0]; a0[1] = biasp[0];
        a1[0] = biasp[1]; a1[1] = biasp[1];
        a2[0] = biasp[2]; a2[1] = biasp[2];
        a3[0] = biasp[3]; a3[1] = biasp[3];

        // input contribution: + W_ih * x(t)
#pragma unroll
        for (int i = 0; i < 3; i++) {
            const ulonglong2 xv = *(const ulonglong2*)&S->xsh[A][i][4 * rg];
            a0[0] = fma2(xv.x, wih2[0][i], a0[0]);  a0[1] = fma2(xv.y, wih2[0][i], a0[1]);
            a1[0] = fma2(xv.x, wih2[1][i], a1[0]);  a1[1] = fma2(xv.y, wih2[1][i], a1[1]);
            a2[0] = fma2(xv.x, wih2[2][i], a2[0]);  a2[1] = fma2(xv.y, wih2[2][i], a2[1]);
            a3[0] = fma2(xv.x, wih2[3][i], a3[0]);  a3[1] = fma2(xv.y, wih2[3][i], a3[1]);
        }

        // recurrent matvec: per k, 3x LDS.128 + 8x fma.rn.f32x2
        {
            const float* hrow = &S->hsh[A][0][4 * rg];
            const ulonglong2* w01p = &S->W01[0][u];
            const ulonglong2* w23p = &S->W23[0][u];
#pragma unroll 4
            for (int k = 0; k < H_; k++) {
                const ulonglong2 hv  = *(const ulonglong2*)(hrow);   // 4 rows
                const ulonglong2 w01 = w01p[k * H_];
                const ulonglong2 w23 = w23p[k * H_];
                a0[0] = fma2(hv.x, w01.x, a0[0]);
                a0[1] = fma2(hv.y, w01.x, a0[1]);
                a1[0] = fma2(hv.x, w01.y, a1[0]);
                a1[1] = fma2(hv.y, w01.y, a1[1]);
                a2[0] = fma2(hv.x, w23.x, a2[0]);
                a2[1] = fma2(hv.y, w23.x, a2[1]);
                a3[0] = fma2(hv.x, w23.y, a3[0]);
                a3[1] = fma2(hv.y, w23.y, a3[1]);
                hrow += HP;
            }
        }

        // nonlinearities + state update on 4 (row, unit u) cells
        float hout[4];
#pragma unroll
        for (int pr = 0; pr < 2; pr++) {
            float gi0, gi1, gf0, gf1, gg0, gg1, go0, go1;
            unpack2(a0[pr], gi0, gi1);
            unpack2(a1[pr], gf0, gf1);
            unpack2(a2[pr], gg0, gg1);
            unpack2(a3[pr], go0, go1);
            {
                const float ig = sigf(gi0), fg = sigf(gf0), gg = tanhfast(gg0), og = sigf(go0);
                const float cn = fmaf(fg, c[2 * pr], ig * gg);
                c[2 * pr] = cn;
                hout[2 * pr] = og * tanhfast(cn);
            }
            {
                const float ig = sigf(gi1), fg = sigf(gf1), gg = tanhfast(gg1), og = sigf(go1);
                const float cn = fmaf(fg, c[2 * pr + 1], ig * gg);
                c[2 * pr + 1] = cn;
                hout[2 * pr + 1] = og * tanhfast(cn);
            }
        }
        *(float4*)&S->hsh[Bb][u][4 * rg] = make_float4(hout[0], hout[1], hout[2], hout[3]);

        // stage x(t+1)
        if (tid < 96) S->xsh[Bb][dro][drr] = xp;

        __syncthreads();
    }

    // epilogue: decode h(T-1) (buffer 0 after the last flip)
    if (tid < 96) {
        const float* hp_ = &S->hsh[0][0][drr];
        const float* wd  = &S->wdec[dro][0];
        float s0 = 0.f, s1 = 0.f, s2 = 0.f, s3 = 0.f;
#pragma unroll 4
        for (int k = 0; k < H_; k += 4) {
            s0 = fmaf(hp_[(k + 0) * HP], wd[k + 0], s0);
            s1 = fmaf(hp_[(k + 1) * HP], wd[k + 1], s1);
            s2 = fmaf(hp_[(k + 2) * HP], wd[k + 2], s2);
            s3 = fmaf(hp_[(k + 3) * HP], wd[k + 3], s3);
        }
        out[((size_t)(row0 + drr) * T_ + (T_ - 1)) * 3 + dro] = (s0 + s1) + (s2 + s3) + bd;
    }
}

extern "C" void kernel_launch(void* const* d_in, const int* in_sizes, int n_in,
                              void* d_out, int out_size) {
    const float* x    = (const float*)d_in[0];
    const float* Wih  = (const float*)d_in[1];
    const float* Whh  = (const float*)d_in[2];
    const float* bih  = (const float*)d_in[3];
    const float* bhh  = (const float*)d_in[4];
    const float* Wdec = (const float*)d_in[5];
    const float* bdec = (const float*)d_in[6];
    float* out = (float*)d_out;

    cudaFuncSetAttribute(lstm_persistent_kernel,
                         cudaFuncAttributeMaxDynamicSharedMemorySize, SMEM_BYTES);
    lstm_persistent_kernel<<<B_ / RT, NT, SMEM_BYTES>>>(x, Wih, Whh, bih, bhh, Wdec, bdec, out);
}